// round 1
// baseline (speedup 1.0000x reference)
#include <cuda_runtime.h>
#include <cuda_bf16.h>

// Problem constants (fixed by the dataset problem)
#define Bb 2
#define Nn 4
#define Dd 48
#define Hh 28
#define Ww 60
#define Cc 64
#define NXc 192
#define NYc 192
#define NZc 1
#define Mcells (NYc * NXc)
#define DMINf 2.0f
#define F_BEV 4.0f      // 1/SCALE
#define CX_BEV 96.0f    // NX/2 + OFFSETX
#define CY_BEV 96.0f    // NY/2

// combine (3x3) + trans (3) per (b,n)
__device__ float g_comb[Bb * Nn][12];

// ---------------------------------------------------------------------------
// Prep: combine = R @ inv(K), trans = pose[:3,3]. fp64 inverse -> fp32.
// For the given K (upper-triangular with exact entries) this matches the
// fp32 LU result bit-for-bit (every relevant entry is a single rounded div).
// ---------------------------------------------------------------------------
__global__ void prep_kernel(const float* __restrict__ intr,
                            const float* __restrict__ pose) {
    int bn = threadIdx.x;
    if (bn >= Bb * Nn) return;
    const float* K = intr + bn * 9;
    const float* P = pose + bn * 16;

    double a00 = K[0], a01 = K[1], a02 = K[2];
    double a10 = K[3], a11 = K[4], a12 = K[5];
    double a20 = K[6], a21 = K[7], a22 = K[8];
    double det = a00 * (a11 * a22 - a12 * a21)
               - a01 * (a10 * a22 - a12 * a20)
               + a02 * (a10 * a21 - a11 * a20);
    double id = 1.0 / det;
    double i00 = (a11 * a22 - a12 * a21) * id;
    double i01 = (a02 * a21 - a01 * a22) * id;
    double i02 = (a01 * a12 - a02 * a11) * id;
    double i10 = (a12 * a20 - a10 * a22) * id;
    double i11 = (a00 * a22 - a02 * a20) * id;
    double i12 = (a02 * a10 - a00 * a12) * id;
    double i20 = (a10 * a21 - a11 * a20) * id;
    double i21 = (a01 * a20 - a00 * a21) * id;
    double i22 = (a00 * a11 - a01 * a10) * id;

    double r00 = P[0], r01 = P[1], r02 = P[2];
    double r10 = P[4], r11 = P[5], r12 = P[6];
    double r20 = P[8], r21 = P[9], r22 = P[10];

    float* cb = g_comb[bn];
    cb[0] = (float)(r00 * i00 + r01 * i10 + r02 * i20);
    cb[1] = (float)(r00 * i01 + r01 * i11 + r02 * i21);
    cb[2] = (float)(r00 * i02 + r01 * i12 + r02 * i22);
    cb[3] = (float)(r10 * i00 + r11 * i10 + r12 * i20);
    cb[4] = (float)(r10 * i01 + r11 * i11 + r12 * i21);
    cb[5] = (float)(r10 * i02 + r11 * i12 + r12 * i22);
    cb[6] = (float)(r20 * i00 + r21 * i10 + r22 * i20);
    cb[7] = (float)(r20 * i01 + r21 * i11 + r22 * i21);
    cb[8] = (float)(r20 * i02 + r21 * i12 + r22 * i22);
    cb[9]  = P[3];
    cb[10] = P[7];
    cb[11] = P[11];
}

// ---------------------------------------------------------------------------
// Zero output (poisoned to 0xAA by the harness)
// ---------------------------------------------------------------------------
__global__ void zero_kernel(float4* __restrict__ out, int n4) {
    int i = blockIdx.x * blockDim.x + threadIdx.x;
    if (i < n4) out[i] = make_float4(0.f, 0.f, 0.f, 0.f);
}

// ---------------------------------------------------------------------------
// Scatter: one warp per (b,n,d,w) column, loop over h (28).
//  - lane L computes the cell key for h=L in phase 1 (lanes 28..31 idle)
//  - phase 2 broadcasts key via shfl; each lane accumulates 2 channels
//    (float2) in registers while the cell key is unchanged; atomicAdd only
//    on cell change / at the end.
// Index arithmetic is rounding-pinned to match the JAX fp32 reference.
// ---------------------------------------------------------------------------
__global__ void __launch_bounds__(256)
scatter_kernel(const float* __restrict__ x, float* __restrict__ out) {
    const int lane = threadIdx.x & 31;
    const int col = blockIdx.x * 8 + (threadIdx.x >> 5);  // (bn,dI,w)

    const int w  = col % Ww;
    int t        = col / Ww;
    const int dI = t % Dd;
    const int bn = t / Dd;
    const int b  = bn / Nn;

    const float* cb = g_comb[bn];
    const float c00 = cb[0], c01 = cb[1], c02 = cb[2];
    const float c10 = cb[3], c11 = cb[4], c12 = cb[5];
    const float c20 = cb[6], c21 = cb[7], c22 = cb[8];
    const float t0 = cb[9], t1 = cb[10], t2 = cb[11];

    const float dval = __fadd_rn(DMINf, (float)dI);           // arange: 2 + i
    const float du = 479.0f / 59.0f;                          // linspace step (fp32 div)
    const float dvstep = 223.0f / 27.0f;
    const float u  = __fmul_rn((float)w, du);                 // i * step
    const float ud = __fmul_rn(u, dval);                      // pts[...,0] = u*d

    // ---- phase 1: lane computes key for h = lane ----
    int myKey = -1;
    if (lane < Hh) {
        const float v  = __fmul_rn((float)lane, dvstep);
        const float vd = __fmul_rn(v, dval);                  // pts[...,1] = v*d
        // einsum: ascending-k fma chain, then + trans (separate rounded add)
        const float g0 = __fadd_rn(fmaf(c02, dval, fmaf(c01, vd, __fmul_rn(c00, ud))), t0);
        const float g1 = __fadd_rn(fmaf(c12, dval, fmaf(c11, vd, __fmul_rn(c10, ud))), t1);
        const float g2 = __fadd_rn(fmaf(c22, dval, fmaf(c21, vd, __fmul_rn(c20, ud))), t2);
        const int gx = (int)(fmaf(g0, F_BEV, CX_BEV));        // *4 exact; trunc = rzi
        const int gy = (int)(fmaf(g1, F_BEV, CY_BEV));
        const int gz = (int)(__fdiv_rn(__fadd_rn(g2, 10.0f), 20.0f));
        if (gx >= 0 && gx < NXc && gy >= 0 && gy < NYc && gz >= 0 && gz < NZc) {
            myKey = (b * NZc + gz) * (Cc * Mcells) + gy * NXc + gx;
        }
    }

    // ---- phase 2: accumulate over h ----
    const float2* xp = (const float2*)(x
        + ((size_t)(bn * Dd + dI) * Hh * Ww + w) * Cc) + lane;  // 2 channels / lane
    const size_t hstride = (size_t)Ww * Cc / 2;                 // float2 stride per h

    float2 acc = make_float2(0.f, 0.f);
    int curKey = -1;
    float* outc = out + 2 * lane * Mcells;                       // channel 2*lane base

    #pragma unroll 4
    for (int h = 0; h < Hh; ++h) {
        const int key = __shfl_sync(0xffffffffu, myKey, h);
        if (key >= 0) {
            const float2 xv = xp[h * hstride];
            if (key == curKey) {
                acc.x += xv.x;
                acc.y += xv.y;
            } else {
                if (curKey >= 0) {
                    atomicAdd(outc + curKey,          acc.x);
                    atomicAdd(outc + curKey + Mcells, acc.y);
                }
                curKey = key;
                acc = xv;
            }
        }
    }
    if (curKey >= 0) {
        atomicAdd(outc + curKey,          acc.x);
        atomicAdd(outc + curKey + Mcells, acc.y);
    }
}

// ---------------------------------------------------------------------------
extern "C" void kernel_launch(void* const* d_in, const int* in_sizes, int n_in,
                              void* d_out, int out_size) {
    const float* x    = (const float*)d_in[0];
    const float* intr = (const float*)d_in[1];
    const float* pose = (const float*)d_in[2];
    float* out = (float*)d_out;

    prep_kernel<<<1, 32>>>(intr, pose);

    int n4 = out_size / 4;  // 4,718,592 / 4
    zero_kernel<<<(n4 + 255) / 256, 256>>>((float4*)out, n4);

    // B*N*D*W = 23040 columns, 8 columns (warps) per 256-thread block
    scatter_kernel<<<(Bb * Nn * Dd * Ww) / 8, 256>>>(x, out);
}

// round 2
// speedup vs baseline: 1.8632x; 1.8632x over previous
#include <cuda_runtime.h>
#include <cuda_bf16.h>

// Problem constants (fixed by the dataset problem)
#define Bb 2
#define Nn 4
#define Dd 48
#define Hh 28
#define Ww 60
#define Cc 64
#define NXc 192
#define NYc 192
#define NZc 1
#define Mcells (NYc * NXc)
#define DMINf 2.0f
#define F_BEV 4.0f      // 1/SCALE
#define CX_BEV 96.0f    // NX/2 + OFFSETX
#define CY_BEV 96.0f    // NY/2

// combine (3x3) + trans (3) per (b,n)
__device__ float g_comb[Bb * Nn][12];

// ---------------------------------------------------------------------------
// Fused zero + prep: grid-stride zero of out; block 0 lanes 0..7 additionally
// compute combine = R @ inv(K) (fp64 -> fp32) and trans = pose[:3,3].
// ---------------------------------------------------------------------------
__global__ void __launch_bounds__(256)
zero_prep_kernel(float4* __restrict__ out, int n4,
                 const float* __restrict__ intr,
                 const float* __restrict__ pose) {
    if (blockIdx.x == 0 && threadIdx.x < Bb * Nn) {
        const int bn = threadIdx.x;
        const float* K = intr + bn * 9;
        const float* P = pose + bn * 16;

        double a00 = K[0], a01 = K[1], a02 = K[2];
        double a10 = K[3], a11 = K[4], a12 = K[5];
        double a20 = K[6], a21 = K[7], a22 = K[8];
        double det = a00 * (a11 * a22 - a12 * a21)
                   - a01 * (a10 * a22 - a12 * a20)
                   + a02 * (a10 * a21 - a11 * a20);
        double id = 1.0 / det;
        double i00 = (a11 * a22 - a12 * a21) * id;
        double i01 = (a02 * a21 - a01 * a22) * id;
        double i02 = (a01 * a12 - a02 * a11) * id;
        double i10 = (a12 * a20 - a10 * a22) * id;
        double i11 = (a00 * a22 - a02 * a20) * id;
        double i12 = (a02 * a10 - a00 * a12) * id;
        double i20 = (a10 * a21 - a11 * a20) * id;
        double i21 = (a01 * a20 - a00 * a21) * id;
        double i22 = (a00 * a11 - a01 * a10) * id;

        double r00 = P[0], r01 = P[1], r02 = P[2];
        double r10 = P[4], r11 = P[5], r12 = P[6];
        double r20 = P[8], r21 = P[9], r22 = P[10];

        float* cb = g_comb[bn];
        cb[0] = (float)(r00 * i00 + r01 * i10 + r02 * i20);
        cb[1] = (float)(r00 * i01 + r01 * i11 + r02 * i21);
        cb[2] = (float)(r00 * i02 + r01 * i12 + r02 * i22);
        cb[3] = (float)(r10 * i00 + r11 * i10 + r12 * i20);
        cb[4] = (float)(r10 * i01 + r11 * i11 + r12 * i21);
        cb[5] = (float)(r10 * i02 + r11 * i12 + r12 * i22);
        cb[6] = (float)(r20 * i00 + r21 * i10 + r22 * i20);
        cb[7] = (float)(r20 * i01 + r21 * i11 + r22 * i21);
        cb[8] = (float)(r20 * i02 + r21 * i12 + r22 * i22);
        cb[9]  = P[3];
        cb[10] = P[7];
        cb[11] = P[11];
    }

    int i = blockIdx.x * blockDim.x + threadIdx.x;
    if (i < n4) out[i] = make_float4(0.f, 0.f, 0.f, 0.f);
}

// ---------------------------------------------------------------------------
// Scatter: one warp per (b,n,d,w) column, loop over h (28).
//  phase 1: lane L computes the cell key for h=L (lanes 28..31 -> -1)
//  phase 2:
//    - ballot: if no lane kept, warp exits immediately (56% of columns)
//    - if all kept lanes share one key (dominant case for this geometry,
//      detected generically): 28 independent predicated float2 loads fully
//      unrolled (high MLP), 2 atomics total per lane
//    - else: run-length merged ffs loop over kept bits (general case)
// Index arithmetic is rounding-pinned to match the JAX fp32 reference.
// ---------------------------------------------------------------------------
__global__ void __launch_bounds__(256)
scatter_kernel(const float* __restrict__ x, float* __restrict__ out) {
    const int lane = threadIdx.x & 31;
    const int col = blockIdx.x * 8 + (threadIdx.x >> 5);  // (bn,dI,w)

    const int w  = col % Ww;
    int t        = col / Ww;
    const int dI = t % Dd;
    const int bn = t / Dd;
    const int b  = bn / Nn;

    const float* cb = g_comb[bn];

    const float dval = __fadd_rn(DMINf, (float)dI);           // arange: 2 + i
    const float du = 479.0f / 59.0f;                          // linspace step (fp32 div)
    const float dvstep = 223.0f / 27.0f;
    const float u  = __fmul_rn((float)w, du);                 // i * step
    const float ud = __fmul_rn(u, dval);                      // pts[...,0] = u*d

    // ---- phase 1: lane computes key for h = lane ----
    int myKey = -1;
    if (lane < Hh) {
        const float v  = __fmul_rn((float)lane, dvstep);
        const float vd = __fmul_rn(v, dval);                  // pts[...,1] = v*d
        // einsum: ascending-k fma chain, then + trans (separate rounded add)
        const float g0 = __fadd_rn(fmaf(cb[2], dval, fmaf(cb[1], vd, __fmul_rn(cb[0], ud))), cb[9]);
        const float g1 = __fadd_rn(fmaf(cb[5], dval, fmaf(cb[4], vd, __fmul_rn(cb[3], ud))), cb[10]);
        const float g2 = __fadd_rn(fmaf(cb[8], dval, fmaf(cb[7], vd, __fmul_rn(cb[6], ud))), cb[11]);
        const int gx = (int)(fmaf(g0, F_BEV, CX_BEV));        // trunc = rzi (astype int32)
        const int gy = (int)(fmaf(g1, F_BEV, CY_BEV));
        const int gz = (int)(__fdiv_rn(__fadd_rn(g2, 10.0f), 20.0f));
        if (gx >= 0 && gx < NXc && gy >= 0 && gy < NYc && gz >= 0 && gz < NZc) {
            myKey = (b * NZc + gz) * (Cc * Mcells) + gy * NXc + gx;
        }
    }

    const unsigned fullm = 0xffffffffu;
    const unsigned mask = __ballot_sync(fullm, myKey >= 0);
    if (mask == 0u) return;                                   // whole column culled

    // ---- phase 2: accumulate over kept h ----
    const float2* xp = (const float2*)(x
        + ((size_t)(bn * Dd + dI) * Hh * Ww + w) * Cc) + lane;  // 2 channels / lane
    const size_t hstride = (size_t)Ww * Cc / 2;                 // float2 stride per h
    float* outc = out + 2 * lane * Mcells;                      // channel 2*lane base

    const int leader = __ffs(mask) - 1;
    const int key0 = __shfl_sync(fullm, myKey, leader);
    const bool same = (myKey < 0) | (myKey == key0);

    if (__all_sync(fullm, same)) {
        // Fast path: single destination cell. Independent predicated loads.
        float ax0 = 0.f, ay0 = 0.f, ax1 = 0.f, ay1 = 0.f;
        #pragma unroll
        for (int h = 0; h < Hh; h += 2) {
            if ((mask >> h) & 1u) {
                const float2 v = xp[h * hstride];
                ax0 += v.x; ay0 += v.y;
            }
            if ((mask >> (h + 1)) & 1u) {
                const float2 v = xp[(h + 1) * hstride];
                ax1 += v.x; ay1 += v.y;
            }
        }
        atomicAdd(outc + key0,          ax0 + ax1);
        atomicAdd(outc + key0 + Mcells, ay0 + ay1);
    } else {
        // General path: run-length merge over kept bits.
        float2 acc = make_float2(0.f, 0.f);
        int curKey = -1;
        unsigned m = mask;
        while (m) {
            const int h = __ffs(m) - 1;
            m &= m - 1;
            const int key = __shfl_sync(fullm, myKey, h);
            const float2 xv = xp[h * hstride];
            if (key == curKey) {
                acc.x += xv.x; acc.y += xv.y;
            } else {
                if (curKey >= 0) {
                    atomicAdd(outc + curKey,          acc.x);
                    atomicAdd(outc + curKey + Mcells, acc.y);
                }
                curKey = key;
                acc = xv;
            }
        }
        if (curKey >= 0) {
            atomicAdd(outc + curKey,          acc.x);
            atomicAdd(outc + curKey + Mcells, acc.y);
        }
    }
}

// ---------------------------------------------------------------------------
extern "C" void kernel_launch(void* const* d_in, const int* in_sizes, int n_in,
                              void* d_out, int out_size) {
    const float* x    = (const float*)d_in[0];
    const float* intr = (const float*)d_in[1];
    const float* pose = (const float*)d_in[2];
    float* out = (float*)d_out;

    const int n4 = out_size / 4;  // 4,718,592 / 4 = 1,179,648 float4
    zero_prep_kernel<<<(n4 + 255) / 256, 256>>>((float4*)out, n4, intr, pose);

    // B*N*D*W = 23040 columns (warps), 8 warps per 256-thread block
    scatter_kernel<<<(Bb * Nn * Dd * Ww) / 8, 256>>>(x, out);
}